// round 4
// baseline (speedup 1.0000x reference)
#include <cuda_runtime.h>

// Resampling_79353815760907
// input_fmap: (B=16, P=4, H=32, W=32, D=32, C=8) float32
// theta:      (B=16, P=4, 3, 4) float32
// out:        (B, P, H, W, D, C) float32
//
// Round 4 (= round 3 resubmitted after infra failure):
//  - 2 threads/point (4 channels each) for packed L1 wavefronts
//  - theta loaded as 3x float4 (was 12 scalar LDGs)
//  - all 8 corner float4s loaded into registers up front (MLP=8), blend after
//  - corner offsets built from shared partial sums; launch_bounds relaxed so
//    ptxas can hold all corners in flight
//
// Reference semantics (kept faithfully, including quirks):
//   x = t00*w + t01*h + t02*d + t03 + 2  (rows 1,2 for y,z)
//   x0 = clip(floor(x), 0, 34); x1 = x0+1 (NOT re-clipped)
//   gather padded[b,p, xi, yi, zi, :]  -- xi indexes the H axis (cross-wired)
//   padded = pad 2 each side -> orig index = xi-2, zero outside [0,32)
//   xd = x - x0 (post-clip), trilinear blend.

#define BB 16
#define PP 4
#define HH 32
#define WW 32
#define DD 32
#define CC 8

__global__ void __launch_bounds__(256)
resample_kernel(const float* __restrict__ fmap,
                const float* __restrict__ theta,
                float* __restrict__ out) {
    const int g    = blockIdx.x * blockDim.x + threadIdx.x;  // 2 threads / point
    const int half4 = (g & 1) << 2;  // 0 -> channels 0..3, 4 -> channels 4..7
    const int idx  = g >> 1;         // spatial point over B*P*H*W*D

    const int d  = idx & 31;
    const int w  = (idx >> 5) & 31;
    const int h  = (idx >> 10) & 31;
    const int bp = idx >> 15;        // b*P + p in [0, 64)

    // theta rows as float4: t0=(t00,t01,t02,t03), t1=row1, t2=row2
    const float4* __restrict__ th4 = (const float4*)(theta + bp * 12);
    const float4 t0 = __ldg(th4 + 0);
    const float4 t1 = __ldg(th4 + 1);
    const float4 t2 = __ldg(th4 + 2);

    const float fw = (float)w, fh = (float)h, fd = (float)d;

    const float x = fmaf(t0.x, fw, fmaf(t0.y, fh, fmaf(t0.z, fd, t0.w))) + 2.0f;
    const float y = fmaf(t1.x, fw, fmaf(t1.y, fh, fmaf(t1.z, fd, t1.w))) + 2.0f;
    const float z = fmaf(t2.x, fw, fmaf(t2.y, fh, fmaf(t2.z, fd, t2.w))) + 2.0f;

    // clip(floor, 0, H+2=34)
    const int x0 = min(max((int)floorf(x), 0), 34);
    const int y0 = min(max((int)floorf(y), 0), 34);
    const int z0 = min(max((int)floorf(z), 0), 34);

    const float xd = x - (float)x0;
    const float yd = y - (float)y0;
    const float zd = z - (float)z0;

    const float wx1 = xd, wx0 = 1.0f - xd;
    const float wy1 = yd, wy0 = 1.0f - yd;
    const float wz1 = zd, wz0 = 1.0f - zd;

    // padded -> original indices (pad = 2)
    const int ox0 = x0 - 2, ox1 = ox0 + 1;
    const int oy0 = y0 - 2, oy1 = oy0 + 1;
    const int oz0 = z0 - 2, oz1 = oz0 + 1;

    const bool vx0 = (unsigned)ox0 < 32u, vx1 = (unsigned)ox1 < 32u;
    const bool vy0 = (unsigned)oy0 < 32u, vy1 = (unsigned)oy1 < 32u;
    const bool vz0 = (unsigned)oz0 < 32u, vz1 = (unsigned)oz1 < 32u;

    // axis offsets in floats (xi indexes H axis: stride 32*32*8 = 8192 floats)
    const int X0 = ox0 << 13, X1 = X0 + (1 << 13);
    const int Y0 = oy0 << 8,  Y1 = Y0 + (1 << 8);
    const int Z0 = oz0 << 3,  Z1 = Z0 + (1 << 3);

    const int XY00 = X0 + Y0, XY01 = X0 + Y1, XY10 = X1 + Y0, XY11 = X1 + Y1;

    // base for this (b,p) plus this thread's 16-byte half of the channel vector
    const float* __restrict__ base =
        fmap + (size_t)bp * (HH * WW * DD * CC) + half4;

    const float4 zero4 = make_float4(0.f, 0.f, 0.f, 0.f);

    // ---- batched corner loads: all 8 issued before any blend consumes them ----
    float4 c000 = zero4, c001 = zero4, c010 = zero4, c011 = zero4;
    float4 c100 = zero4, c101 = zero4, c110 = zero4, c111 = zero4;

    const bool vy0z0 = vy0 && vz0, vy0z1 = vy0 && vz1;
    const bool vy1z0 = vy1 && vz0, vy1z1 = vy1 && vz1;

    if (vx0 && vy0z0) c000 = __ldg((const float4*)(base + XY00 + Z0));
    if (vx0 && vy0z1) c001 = __ldg((const float4*)(base + XY00 + Z1));
    if (vx0 && vy1z0) c010 = __ldg((const float4*)(base + XY01 + Z0));
    if (vx0 && vy1z1) c011 = __ldg((const float4*)(base + XY01 + Z1));
    if (vx1 && vy0z0) c100 = __ldg((const float4*)(base + XY10 + Z0));
    if (vx1 && vy0z1) c101 = __ldg((const float4*)(base + XY10 + Z1));
    if (vx1 && vy1z0) c110 = __ldg((const float4*)(base + XY11 + Z0));
    if (vx1 && vy1z1) c111 = __ldg((const float4*)(base + XY11 + Z1));

    // ---- weights ----
    const float wyz00 = wy0 * wz0, wyz01 = wy0 * wz1;
    const float wyz10 = wy1 * wz0, wyz11 = wy1 * wz1;

    const float w000 = wx0 * wyz00, w001 = wx0 * wyz01;
    const float w010 = wx0 * wyz10, w011 = wx0 * wyz11;
    const float w100 = wx1 * wyz00, w101 = wx1 * wyz01;
    const float w110 = wx1 * wyz10, w111 = wx1 * wyz11;

    // ---- blend ----
    float4 acc;
    acc.x = w000 * c000.x; acc.y = w000 * c000.y;
    acc.z = w000 * c000.z; acc.w = w000 * c000.w;

    #define ACC(ww_, c)                                                          \
        acc.x = fmaf(ww_, c.x, acc.x); acc.y = fmaf(ww_, c.y, acc.y);            \
        acc.z = fmaf(ww_, c.z, acc.z); acc.w = fmaf(ww_, c.w, acc.w);

    ACC(w001, c001) ACC(w010, c010) ACC(w011, c011)
    ACC(w100, c100) ACC(w101, c101) ACC(w110, c110) ACC(w111, c111)
    #undef ACC

    float4* __restrict__ o = (float4*)(out + ((size_t)idx << 3) + half4);
    *o = acc;
}

extern "C" void kernel_launch(void* const* d_in, const int* in_sizes, int n_in,
                              void* d_out, int out_size) {
    const float* fmap  = (const float*)d_in[0];
    const float* theta = (const float*)d_in[1];
    float* out = (float*)d_out;

    const int total_threads = BB * PP * HH * WW * DD * 2;  // 2 threads / point
    const int threads = 256;
    const int blocks = total_threads / threads;            // 16384
    resample_kernel<<<blocks, threads>>>(fmap, theta, out);
}

// round 5
// speedup vs baseline: 1.0926x; 1.0926x over previous
#include <cuda_runtime.h>

// Resampling_79353815760907
// input_fmap: (B=16, P=4, H=32, W=32, D=32, C=8) float32
// theta:      (B=16, P=4, 3, 4) float32   out: (B,P,H,W,D,C) float32
//
// Round 5: h-walk with corner-plane register reuse.
//   gather index on the W axis is y = row1.(w,h,d) ~ h  (theta ~ identity),
//   so walking h at fixed (bp,w,d) advances y0 by +1 per step: the previous
//   y1-plane (4 corners) becomes the new y0-plane. Double-buffered float4
//   slots with unroll-2 role swap -> 4 unconditional loads/step + 4
//   predicated reloads when reuse breaks (x0/z0 drift, y-jump, clip).
//   OOB handling: loads always in-bounds via &31 wrap; reference zero-pad
//   reproduced by zeroing the per-axis weights (6 FSEL), no zero-init MOVs.
//   Columns split into 8-step segments for wave balance (2048 blocks).
//
// Reference semantics preserved:
//   x = t00*w + t01*h + t02*d + t03 + 2  (rows 1,2 -> y,z)
//   x0 = clip(floor(x),0,34); x1 = x0+1 (not re-clipped)
//   gather padded[b,p, xi, yi, zi] (xi on H axis); orig = idx-2, zero OOB
//   xd = x - x0 (post-clip), trilinear blend.

__global__ void __launch_bounds__(256)
resample_kernel(const float* __restrict__ fmap,
                const float* __restrict__ theta,
                float* __restrict__ out) {
    const int g = blockIdx.x * 256 + threadIdx.x;
    const int half4 = (g & 1) << 2;   // 0: ch 0..3, 4: ch 4..7
    const int d   = (g >> 1) & 31;
    const int w   = (g >> 6) & 31;
    const int seg = (g >> 11) & 3;    // 8-step h segment
    const int bp  = g >> 13;          // b*P + p

    const float4* __restrict__ th4 = (const float4*)(theta + bp * 12);
    const float4 t0 = __ldg(th4 + 0);
    const float4 t1 = __ldg(th4 + 1);
    const float4 t2 = __ldg(th4 + 2);

    const float fw = (float)w, fd = (float)d;
    // per-column bases: coord(h) = tX.y * h + base
    const float xb = fmaf(t0.x, fw, fmaf(t0.z, fd, t0.w)) + 2.0f;
    const float yb = fmaf(t1.x, fw, fmaf(t1.z, fd, t1.w)) + 2.0f;
    const float zb = fmaf(t2.x, fw, fmaf(t2.z, fd, t2.w)) + 2.0f;

    const float* __restrict__ base = fmap + bp * 262144 + half4;

    int h = seg << 3;
    float* __restrict__ optr =
        out + bp * 262144 + h * 8192 + w * 256 + (d << 3) + half4;

    int px0 = -100, py0 = -100, pz0 = -100;   // force fresh on first step
    const float4 z4 = make_float4(0.f, 0.f, 0.f, 0.f);
    float4 A00 = z4, A01 = z4, A10 = z4, A11 = z4;   // plane slot A
    float4 B00 = z4, B01 = z4, B10 = z4, B11 = z4;   // plane slot B

    // P** = y0-plane slot (reused from prev step's y1), Q** = y1-plane slot
    auto step = [&](float4& P00, float4& P01, float4& P10, float4& P11,
                    float4& Q00, float4& Q01, float4& Q10, float4& Q11) {
        const float fh = (float)h;
        const float x = fmaf(t0.y, fh, xb);
        const float y = fmaf(t1.y, fh, yb);
        const float z = fmaf(t2.y, fh, zb);

        const int x0 = min(max((int)floorf(x), 0), 34);
        const int y0 = min(max((int)floorf(y), 0), 34);
        const int z0 = min(max((int)floorf(z), 0), 34);

        const bool fresh = (x0 != px0) | (z0 != pz0) | (y0 != py0 + 1);
        px0 = x0; py0 = y0; pz0 = z0;

        const float xd = x - (float)x0;
        const float yd = y - (float)y0;
        const float zd = z - (float)z0;

        float wx0 = 1.f - xd, wx1 = xd;
        float wy0 = 1.f - yd, wy1 = yd;
        float wz0 = 1.f - zd, wz1 = zd;
        // reference zero-pad: zero the weight of any OOB axis index
        if ((unsigned)(x0 - 2) >= 32u) wx0 = 0.f;
        if ((unsigned)(x0 - 1) >= 32u) wx1 = 0.f;
        if ((unsigned)(y0 - 2) >= 32u) wy0 = 0.f;
        if ((unsigned)(y0 - 1) >= 32u) wy1 = 0.f;
        if ((unsigned)(z0 - 2) >= 32u) wz0 = 0.f;
        if ((unsigned)(z0 - 1) >= 32u) wz1 = 0.f;

        // always-in-bounds offsets (value irrelevant when weight is 0)
        const int HX0 = ((x0 - 2) & 31) << 13, HX1 = ((x0 - 1) & 31) << 13;
        const int WY0 = ((y0 - 2) & 31) << 8,  WY1 = ((y0 - 1) & 31) << 8;
        const int DZ0 = ((z0 - 2) & 31) << 3,  DZ1 = ((z0 - 1) & 31) << 3;

        if (fresh) {  // reload y0-plane only when reuse chain broke
            P00 = __ldg((const float4*)(base + HX0 + WY0 + DZ0));
            P01 = __ldg((const float4*)(base + HX0 + WY0 + DZ1));
            P10 = __ldg((const float4*)(base + HX1 + WY0 + DZ0));
            P11 = __ldg((const float4*)(base + HX1 + WY0 + DZ1));
        }
        Q00 = __ldg((const float4*)(base + HX0 + WY1 + DZ0));
        Q01 = __ldg((const float4*)(base + HX0 + WY1 + DZ1));
        Q10 = __ldg((const float4*)(base + HX1 + WY1 + DZ0));
        Q11 = __ldg((const float4*)(base + HX1 + WY1 + DZ1));

        const float wxz00 = wx0 * wz0, wxz01 = wx0 * wz1;
        const float wxz10 = wx1 * wz0, wxz11 = wx1 * wz1;
        const float a00 = wxz00 * wy0, a01 = wxz01 * wy0;
        const float a10 = wxz10 * wy0, a11 = wxz11 * wy0;
        const float b00 = wxz00 * wy1, b01 = wxz01 * wy1;
        const float b10 = wxz10 * wy1, b11 = wxz11 * wy1;

        float4 acc;
        acc.x = a00 * P00.x; acc.y = a00 * P00.y;
        acc.z = a00 * P00.z; acc.w = a00 * P00.w;
        #define ACC(ww_, c)                                                  \
            acc.x = fmaf(ww_, c.x, acc.x); acc.y = fmaf(ww_, c.y, acc.y);    \
            acc.z = fmaf(ww_, c.z, acc.z); acc.w = fmaf(ww_, c.w, acc.w);
        ACC(a01, P01) ACC(a10, P10) ACC(a11, P11)
        ACC(b00, Q00) ACC(b01, Q01) ACC(b10, Q10) ACC(b11, Q11)
        #undef ACC

        *(float4*)optr = acc;
        optr += 8192;
        ++h;
    };

    #pragma unroll 1
    for (int it = 0; it < 4; ++it) {
        step(A00, A01, A10, A11, B00, B01, B10, B11);
        step(B00, B01, B10, B11, A00, A01, A10, A11);
    }
}

extern "C" void kernel_launch(void* const* d_in, const int* in_sizes, int n_in,
                              void* d_out, int out_size) {
    const float* fmap  = (const float*)d_in[0];
    const float* theta = (const float*)d_in[1];
    float* out = (float*)d_out;

    // threads = B*P * 4 segments * W * D * 2 halves = 524288
    const int blocks = 524288 / 256;   // 2048
    resample_kernel<<<blocks, 256>>>(fmap, theta, out);
}